// round 11
// baseline (speedup 1.0000x reference)
#include <cuda_runtime.h>
#include <cuda_fp16.h>

#define NN 10000
#define NE 640000
#define FI 128
#define FH 128
#define FO 64
#define STRIDE 192
#define HOFF 96

// ---------------- scratch (static __device__, no allocation) ----------------
// g_cnt = [curA | curB | deg_out], one memset zeroes all three
__device__ __align__(16) int g_cnt[3 * NN];
__device__ int g_csr_pad[NN * STRIDE];
__device__ __align__(16) __half g_t1h[NN * FH];  // fp16 x@W1 (unscaled)
__device__ __align__(16) float  g_h1[NN * FH];   // fp32 relu((S rdo*t1)*rdi + b1)
__device__ __align__(16) __half g_t2h[NN * FO];  // fp16 (rdo*h1)@W2

// ---------------- host-side streams/events, created pre-checkpoint ----------
static cudaStream_t g_s2, g_s3;
static cudaEvent_t g_e1, g_eM, g_eS, g_eB;
static struct StreamInit {
    StreamInit() {
        cudaStreamCreateWithFlags(&g_s2, cudaStreamNonBlocking);
        cudaStreamCreateWithFlags(&g_s3, cudaStreamNonBlocking);
        cudaEventCreateWithFlags(&g_e1, cudaEventDisableTiming);
        cudaEventCreateWithFlags(&g_eM, cudaEventDisableTiming);
        cudaEventCreateWithFlags(&g_eS, cudaEventDisableTiming);
        cudaEventCreateWithFlags(&g_eB, cudaEventDisableTiming);
    }
} g_streaminit;

// ---------------- setup ----------------
// src-degree histogram over int4 range [off4, off4+n4) -> g_cnt[2NN+..]
__global__ void k_hist_src(const int4* __restrict__ src4, int off4, int n4) {
    int i = blockIdx.x * blockDim.x + threadIdx.x;
    if (i < n4) {
        int4 s = src4[off4 + i];
        atomicAdd(&g_cnt[2 * NN + s.x], 1);
        atomicAdd(&g_cnt[2 * NN + s.y], 1);
        atomicAdd(&g_cnt[2 * NN + s.z], 1);
        atomicAdd(&g_cnt[2 * NN + s.w], 1);
    }
}

// padded-CSR fill over int4 edge range; writes slots [slotoff, slotoff+96)
__global__ void k_fill_half(const int4* __restrict__ src4, const int4* __restrict__ dst4,
                            int off4, int n4, int curoff, int slotoff) {
    int i = blockIdx.x * blockDim.x + threadIdx.x;
    if (i < n4) {
        int4 s = src4[off4 + i], d = dst4[off4 + i];
        int p0 = atomicAdd(&g_cnt[curoff + d.x], 1);
        int p1 = atomicAdd(&g_cnt[curoff + d.y], 1);
        int p2 = atomicAdd(&g_cnt[curoff + d.z], 1);
        int p3 = atomicAdd(&g_cnt[curoff + d.w], 1);
        if (p0 < HOFF) g_csr_pad[d.x * STRIDE + slotoff + p0] = s.x;
        if (p1 < HOFF) g_csr_pad[d.y * STRIDE + slotoff + p1] = s.y;
        if (p2 < HOFF) g_csr_pad[d.z * STRIDE + slotoff + p2] = s.z;
        if (p3 < HOFF) g_csr_pad[d.w * STRIDE + slotoff + p3] = s.w;
    }
}

// ---------------- GEMM1: Th = fp16( X[n,:128] @ W1[:128,:128] ), no scaling ----
__global__ void k_gemm1(const float* __restrict__ X, const float* __restrict__ W,
                        __half* __restrict__ T) {
    __shared__ float xs[32][128];
    __shared__ float ws[128][64];
    const int t = threadIdx.x;
    const int rowbase = blockIdx.x * 32;
    const int colbase = blockIdx.y * 64;

    for (int i = t; i < 128 * 16; i += 128) {
        int k = i >> 4, c4 = i & 15;
        *(float4*)&ws[k][c4 * 4] = *(const float4*)&W[k * FH + colbase + c4 * 4];
    }
    for (int i = t; i < 32 * 32; i += 128) {
        int r = i >> 5, c4 = i & 31;
        int row = rowbase + r;
        float4 v = make_float4(0.f, 0.f, 0.f, 0.f);
        if (row < NN) v = *(const float4*)&X[row * 128 + c4 * 4];
        *(float4*)&xs[r][c4 * 4] = v;
    }
    __syncthreads();

    const int tx = t & 15, ty = t >> 4;
    const int j0 = tx * 4, r0 = ty * 4;
    float4 acc[4];
    #pragma unroll
    for (int r = 0; r < 4; r++) acc[r] = make_float4(0.f, 0.f, 0.f, 0.f);

    #pragma unroll 4
    for (int k4 = 0; k4 < 32; k4++) {
        float4 a[4], w[4];
        #pragma unroll
        for (int r = 0; r < 4; r++) a[r] = *(float4*)&xs[r0 + r][k4 * 4];
        #pragma unroll
        for (int kk = 0; kk < 4; kk++) w[kk] = *(float4*)&ws[k4 * 4 + kk][j0];
        #pragma unroll
        for (int r = 0; r < 4; r++) {
            acc[r].x = fmaf(a[r].x, w[0].x, fmaf(a[r].y, w[1].x, fmaf(a[r].z, w[2].x, fmaf(a[r].w, w[3].x, acc[r].x))));
            acc[r].y = fmaf(a[r].x, w[0].y, fmaf(a[r].y, w[1].y, fmaf(a[r].z, w[2].y, fmaf(a[r].w, w[3].y, acc[r].y))));
            acc[r].z = fmaf(a[r].x, w[0].z, fmaf(a[r].y, w[1].z, fmaf(a[r].z, w[2].z, fmaf(a[r].w, w[3].z, acc[r].z))));
            acc[r].w = fmaf(a[r].x, w[0].w, fmaf(a[r].y, w[1].w, fmaf(a[r].z, w[2].w, fmaf(a[r].w, w[3].w, acc[r].w))));
        }
    }
    #pragma unroll
    for (int r = 0; r < 4; r++) {
        int row = rowbase + r0 + r;
        if (row < NN) {
            __half2 p0 = __floats2half2_rn(acc[r].x, acc[r].y);
            __half2 p1 = __floats2half2_rn(acc[r].z, acc[r].w);
            uint2 st;
            st.x = *(unsigned*)&p0;
            st.y = *(unsigned*)&p1;
            *(uint2*)&T[row * FH + colbase + j0] = st;
        }
    }
}

// ---------------- GEMM2: T2 = fp16( (rdo[n]*H[n,:128]) @ W2[:128,:64] ) --------
// rdo computed inline from deg_out
__global__ void k_gemm2(const float* __restrict__ X, const float* __restrict__ W,
                        __half* __restrict__ T) {
    __shared__ float xs[32][128];
    __shared__ float ws[128][64];
    const int t = threadIdx.x;
    const int rowbase = blockIdx.x * 32;

    for (int i = t; i < 128 * 16; i += 128) {
        int k = i >> 4, c4 = i & 15;
        *(float4*)&ws[k][c4 * 4] = *(const float4*)&W[k * FO + c4 * 4];
    }
    for (int i = t; i < 32 * 32; i += 128) {
        int r = i >> 5, c4 = i & 31;
        int row = rowbase + r;
        float4 v = make_float4(0.f, 0.f, 0.f, 0.f);
        if (row < NN) {
            v = *(const float4*)&X[row * 128 + c4 * 4];
            float sc = rsqrtf(fmaxf((float)g_cnt[2 * NN + row], 1.0f));
            v.x *= sc; v.y *= sc; v.z *= sc; v.w *= sc;
        }
        *(float4*)&xs[r][c4 * 4] = v;
    }
    __syncthreads();

    const int tx = t & 15, ty = t >> 4;
    const int j0 = tx * 4, r0 = ty * 4;
    float4 acc[4];
    #pragma unroll
    for (int r = 0; r < 4; r++) acc[r] = make_float4(0.f, 0.f, 0.f, 0.f);

    #pragma unroll 4
    for (int k4 = 0; k4 < 32; k4++) {
        float4 a[4], w[4];
        #pragma unroll
        for (int r = 0; r < 4; r++) a[r] = *(float4*)&xs[r0 + r][k4 * 4];
        #pragma unroll
        for (int kk = 0; kk < 4; kk++) w[kk] = *(float4*)&ws[k4 * 4 + kk][j0];
        #pragma unroll
        for (int r = 0; r < 4; r++) {
            acc[r].x = fmaf(a[r].x, w[0].x, fmaf(a[r].y, w[1].x, fmaf(a[r].z, w[2].x, fmaf(a[r].w, w[3].x, acc[r].x))));
            acc[r].y = fmaf(a[r].x, w[0].y, fmaf(a[r].y, w[1].y, fmaf(a[r].z, w[2].y, fmaf(a[r].w, w[3].y, acc[r].y))));
            acc[r].z = fmaf(a[r].x, w[0].z, fmaf(a[r].y, w[1].z, fmaf(a[r].z, w[2].z, fmaf(a[r].w, w[3].z, acc[r].z))));
            acc[r].w = fmaf(a[r].x, w[0].w, fmaf(a[r].y, w[1].w, fmaf(a[r].z, w[2].w, fmaf(a[r].w, w[3].w, acc[r].w))));
        }
    }
    #pragma unroll
    for (int r = 0; r < 4; r++) {
        int row = rowbase + r0 + r;
        if (row < NN) {
            __half2 p0 = __floats2half2_rn(acc[r].x, acc[r].y);
            __half2 p1 = __floats2half2_rn(acc[r].z, acc[r].w);
            uint2 st;
            st.x = *(unsigned*)&p0;
            st.y = *(unsigned*)&p1;
            *(uint2*)&T[row * FO + j0] = st;
        }
    }
}

// ---------------- SpMM layer 1: warp-per-node, per-edge rdo inline -----------
__device__ __forceinline__ void acc_edge(float4& a, uint2 v, float sc) {
    float2 f0 = __half22float2(*reinterpret_cast<__half2*>(&v.x));
    float2 f1 = __half22float2(*reinterpret_cast<__half2*>(&v.y));
    a.x = fmaf(sc, f0.x, a.x); a.y = fmaf(sc, f0.y, a.y);
    a.z = fmaf(sc, f1.x, a.z); a.w = fmaf(sc, f1.y, a.w);
}

__device__ __forceinline__ float edge_sc(int s) {
    return rsqrtf(fmaxf((float)g_cnt[2 * NN + s], 1.0f));
}

__device__ __forceinline__ void gather_sc(const int* __restrict__ row, int n,
                                          const __half* __restrict__ Tc,
                                          float4& a0, float4& a1, float4& a2, float4& a3) {
    int i = 0;
    for (; i + 4 <= n; i += 4) {
        int s0 = row[i], s1 = row[i+1], s2 = row[i+2], s3 = row[i+3];
        uint2 v0 = *(const uint2*)(Tc + s0 * 128);
        uint2 v1 = *(const uint2*)(Tc + s1 * 128);
        uint2 v2 = *(const uint2*)(Tc + s2 * 128);
        uint2 v3 = *(const uint2*)(Tc + s3 * 128);
        float r0 = edge_sc(s0), r1 = edge_sc(s1), r2 = edge_sc(s2), r3 = edge_sc(s3);
        acc_edge(a0, v0, r0); acc_edge(a1, v1, r1);
        acc_edge(a2, v2, r2); acc_edge(a3, v3, r3);
    }
    for (; i < n; i++) {
        int s0 = row[i];
        uint2 v = *(const uint2*)(Tc + s0 * 128);
        acc_edge(a0, v, edge_sc(s0));
    }
}

// layer 1: F=128; per-edge rdo, fused rdi + bias + relu -> fp32 h1
__global__ void k_spmm128(const __half* __restrict__ T, const float* __restrict__ bias,
                          float* __restrict__ out) {
    int gw = (blockIdx.x * blockDim.x + threadIdx.x) >> 5;
    if (gw >= NN) return;
    int lane = threadIdx.x & 31;
    int c = lane * 4;
    const __half* Tc = T + c;
    int dA = g_cnt[gw], dB = g_cnt[NN + gw];
    const int* rowp = g_csr_pad + gw * STRIDE;
    float4 a0 = make_float4(0.f,0.f,0.f,0.f), a1 = a0, a2 = a0, a3 = a0;
    gather_sc(rowp, dA, Tc, a0, a1, a2, a3);
    gather_sc(rowp + HOFF, dB, Tc, a0, a1, a2, a3);
    float rd = rsqrtf(fmaxf((float)(dA + dB), 1.0f));
    float4 b = *(const float4*)(bias + c);
    float4 o;
    o.x = fmaxf(fmaf((a0.x + a1.x) + (a2.x + a3.x), rd, b.x), 0.f);
    o.y = fmaxf(fmaf((a0.y + a1.y) + (a2.y + a3.y), rd, b.y), 0.f);
    o.z = fmaxf(fmaf((a0.z + a1.z) + (a2.z + a3.z), rd, b.z), 0.f);
    o.w = fmaxf(fmaf((a0.w + a1.w) + (a2.w + a3.w), rd, b.w), 0.f);
    *(float4*)(out + gw * 128 + c) = o;
}

// ---------------- final SpMM: F=64 over fp16 t2 ----------------
__global__ void k_spmm64(const __half* __restrict__ T, const float* __restrict__ bias,
                         float* __restrict__ out) {
    int gw = (blockIdx.x * blockDim.x + threadIdx.x) >> 5;
    if (gw >= NN) return;
    int lane = threadIdx.x & 31;
    int c = lane * 2;
    const __half* Tc = T + c;
    int dA = g_cnt[gw], dB = g_cnt[NN + gw];
    const int* rowp = g_csr_pad + gw * STRIDE;
    float2 a0 = make_float2(0.f,0.f), a1 = a0, a2 = a0, a3 = a0;
    #pragma unroll 1
    for (int half = 0; half < 2; half++) {
        const int* rr = rowp + half * HOFF;
        int n = half ? dB : dA;
        int i = 0;
        for (; i + 8 <= n; i += 8) {
            int s0 = rr[i],   s1 = rr[i+1], s2 = rr[i+2], s3 = rr[i+3];
            int s4 = rr[i+4], s5 = rr[i+5], s6 = rr[i+6], s7 = rr[i+7];
            unsigned v0 = *(const unsigned*)(Tc + s0 * 64);
            unsigned v1 = *(const unsigned*)(Tc + s1 * 64);
            unsigned v2 = *(const unsigned*)(Tc + s2 * 64);
            unsigned v3 = *(const unsigned*)(Tc + s3 * 64);
            unsigned v4 = *(const unsigned*)(Tc + s4 * 64);
            unsigned v5 = *(const unsigned*)(Tc + s5 * 64);
            unsigned v6 = *(const unsigned*)(Tc + s6 * 64);
            unsigned v7 = *(const unsigned*)(Tc + s7 * 64);
            float2 f0 = __half22float2(*reinterpret_cast<__half2*>(&v0));
            float2 f1 = __half22float2(*reinterpret_cast<__half2*>(&v1));
            float2 f2 = __half22float2(*reinterpret_cast<__half2*>(&v2));
            float2 f3 = __half22float2(*reinterpret_cast<__half2*>(&v3));
            float2 f4 = __half22float2(*reinterpret_cast<__half2*>(&v4));
            float2 f5 = __half22float2(*reinterpret_cast<__half2*>(&v5));
            float2 f6 = __half22float2(*reinterpret_cast<__half2*>(&v6));
            float2 f7 = __half22float2(*reinterpret_cast<__half2*>(&v7));
            a0.x += f0.x + f4.x; a0.y += f0.y + f4.y;
            a1.x += f1.x + f5.x; a1.y += f1.y + f5.y;
            a2.x += f2.x + f6.x; a2.y += f2.y + f6.y;
            a3.x += f3.x + f7.x; a3.y += f3.y + f7.y;
        }
        for (; i < n; i++) {
            unsigned v = *(const unsigned*)(Tc + rr[i] * 64);
            float2 f = __half22float2(*reinterpret_cast<__half2*>(&v));
            a0.x += f.x; a0.y += f.y;
        }
    }
    float rd = rsqrtf(fmaxf((float)(dA + dB), 1.0f));
    float2 b = *(const float2*)(bias + c);
    float2 o;
    o.x = fmaf((a0.x + a1.x) + (a2.x + a3.x), rd, b.x);
    o.y = fmaf((a0.y + a1.y) + (a2.y + a3.y), rd, b.y);
    *(float2*)(out + gw * 64 + c) = o;
}

// ---------------- launch ----------------
extern "C" void kernel_launch(void* const* d_in, const int* in_sizes, int n_in,
                              void* d_out, int out_size) {
    const float* x   = (const float*)d_in[0];
    const int4*  src = (const int4*)d_in[1];
    const int4*  dst = (const int4*)d_in[2];
    const float* W1  = (const float*)d_in[3];
    const float* b1  = (const float*)d_in[4];
    const float* W2  = (const float*)d_in[5];
    const float* b2  = (const float*)d_in[6];
    float* out = (float*)d_out;

    __half *t1, *t2;
    float *h1;
    int* cnt;
    cudaGetSymbolAddress((void**)&t1, g_t1h);
    cudaGetSymbolAddress((void**)&h1, g_h1);
    cudaGetSymbolAddress((void**)&t2, g_t2h);
    cudaGetSymbolAddress((void**)&cnt, g_cnt);

    const int N4 = NE / 4;
    const int H4 = N4 / 2;

    // fork
    cudaEventRecord(g_e1, 0);
    cudaStreamWaitEvent(g_s2, g_e1, 0);
    cudaStreamWaitEvent(g_s3, g_e1, 0);

    // main: single memset of curA|curB|deg_out, then fillA immediately
    cudaMemsetAsync(cnt, 0, 3 * NN * sizeof(int), 0);
    cudaEventRecord(g_eM, 0);
    k_fill_half<<<(H4 + 255) / 256, 256>>>(src, dst, 0, H4, 0, 0);

    // s2: gemm1 (independent of graph), then histA (after memset)
    k_gemm1<<<dim3((NN + 31) / 32, FH / 64), 128, 0, g_s2>>>(x, W1, t1);
    cudaStreamWaitEvent(g_s2, g_eM, 0);
    k_hist_src<<<(H4 + 255) / 256, 256, 0, g_s2>>>(src, 0, H4);
    cudaEventRecord(g_eS, g_s2);

    // s3: wait memset, histB, fillB
    cudaStreamWaitEvent(g_s3, g_eM, 0);
    k_hist_src<<<(H4 + 255) / 256, 256, 0, g_s3>>>(src, H4, H4);
    k_fill_half<<<(H4 + 255) / 256, 256, 0, g_s3>>>(src, dst, H4, H4, NN, HOFF);
    cudaEventRecord(g_eB, g_s3);

    // main: join, then the 3-kernel dense tail
    cudaStreamWaitEvent(0, g_eS, 0);
    cudaStreamWaitEvent(0, g_eB, 0);
    k_spmm128<<<(NN * 32 + 255) / 256, 256>>>(t1, b1, h1);
    k_gemm2<<<(NN + 31) / 32, 128>>>(h1, W2, t2);
    k_spmm64<<<(NN * 32 + 255) / 256, 256>>>(t2, b2, out);
}

// round 12
// speedup vs baseline: 1.0366x; 1.0366x over previous
#include <cuda_runtime.h>
#include <cuda_fp16.h>

#define NN 10000
#define NE 640000
#define FI 128
#define FH 128
#define FO 64
#define STRIDE 192

// ---------------- scratch (static __device__, no allocation) ----------------
// g_cnt = [cursor/deg_in | deg_out], one memset zeroes both
__device__ __align__(16) int g_cnt[2 * NN];
__device__ int g_csr_pad[NN * STRIDE];
__device__ __align__(16) __half g_t1h[NN * FH];  // fp16 x@W1, then scaled by rdo in place
__device__ __align__(16) float  g_h1[NN * FH];   // fp32 relu((S t1s)*rdi + b1)
__device__ __align__(16) __half g_t2h[NN * FO];  // fp16 (rdo*h1)@W2

// ---------------- host-side stream/events, created pre-checkpoint -----------
static cudaStream_t g_s2;
static cudaEvent_t g_e1, g_eM, g_eS;
static struct StreamInit {
    StreamInit() {
        cudaStreamCreateWithFlags(&g_s2, cudaStreamNonBlocking);
        cudaEventCreateWithFlags(&g_e1, cudaEventDisableTiming);
        cudaEventCreateWithFlags(&g_eM, cudaEventDisableTiming);
        cudaEventCreateWithFlags(&g_eS, cudaEventDisableTiming);
    }
} g_streaminit;

// ---------------- setup ----------------
// full src-degree histogram -> g_cnt[NN..2NN)
__global__ void k_hist(const int4* __restrict__ src4) {
    int i = blockIdx.x * blockDim.x + threadIdx.x;
    if (i < NE / 4) {
        int4 s = src4[i];
        atomicAdd(&g_cnt[NN + s.x], 1);
        atomicAdd(&g_cnt[NN + s.y], 1);
        atomicAdd(&g_cnt[NN + s.z], 1);
        atomicAdd(&g_cnt[NN + s.w], 1);
    }
}

// full padded-CSR fill; cursor in g_cnt[0..NN)
__global__ void k_fill(const int4* __restrict__ src4, const int4* __restrict__ dst4) {
    int i = blockIdx.x * blockDim.x + threadIdx.x;
    if (i < NE / 4) {
        int4 s = src4[i], d = dst4[i];
        int p0 = atomicAdd(&g_cnt[d.x], 1);
        int p1 = atomicAdd(&g_cnt[d.y], 1);
        int p2 = atomicAdd(&g_cnt[d.z], 1);
        int p3 = atomicAdd(&g_cnt[d.w], 1);
        if (p0 < STRIDE) g_csr_pad[d.x * STRIDE + p0] = s.x;
        if (p1 < STRIDE) g_csr_pad[d.y * STRIDE + p1] = s.y;
        if (p2 < STRIDE) g_csr_pad[d.z * STRIDE + p2] = s.z;
        if (p3 < STRIDE) g_csr_pad[d.w * STRIDE + p3] = s.w;
    }
}

// in-place scale t1 rows by rsqrt(max(deg_out,1)); 4 halfs per thread
__global__ void k_scale_t1() {
    int i = blockIdx.x * blockDim.x + threadIdx.x;
    if (i < NN * FH / 4) {
        int row = i >> 5;
        float sc = rsqrtf(fmaxf((float)g_cnt[NN + row], 1.0f));
        uint2 v = *(uint2*)&g_t1h[i * 4];
        float2 f0 = __half22float2(*reinterpret_cast<__half2*>(&v.x));
        float2 f1 = __half22float2(*reinterpret_cast<__half2*>(&v.y));
        f0.x *= sc; f0.y *= sc; f1.x *= sc; f1.y *= sc;
        __half2 h0 = __floats2half2_rn(f0.x, f0.y);
        __half2 h1 = __floats2half2_rn(f1.x, f1.y);
        uint2 o;
        o.x = *(unsigned*)&h0;
        o.y = *(unsigned*)&h1;
        *(uint2*)&g_t1h[i * 4] = o;
    }
}

// ---------------- GEMM1: Th = fp16( X[n,:128] @ W1[:128,:128] ), no scaling ---
__global__ void k_gemm1(const float* __restrict__ X, const float* __restrict__ W,
                        __half* __restrict__ T) {
    __shared__ float xs[32][128];
    __shared__ float ws[128][64];
    const int t = threadIdx.x;
    const int rowbase = blockIdx.x * 32;
    const int colbase = blockIdx.y * 64;

    for (int i = t; i < 128 * 16; i += 128) {
        int k = i >> 4, c4 = i & 15;
        *(float4*)&ws[k][c4 * 4] = *(const float4*)&W[k * FH + colbase + c4 * 4];
    }
    for (int i = t; i < 32 * 32; i += 128) {
        int r = i >> 5, c4 = i & 31;
        int row = rowbase + r;
        float4 v = make_float4(0.f, 0.f, 0.f, 0.f);
        if (row < NN) v = *(const float4*)&X[row * 128 + c4 * 4];
        *(float4*)&xs[r][c4 * 4] = v;
    }
    __syncthreads();

    const int tx = t & 15, ty = t >> 4;
    const int j0 = tx * 4, r0 = ty * 4;
    float4 acc[4];
    #pragma unroll
    for (int r = 0; r < 4; r++) acc[r] = make_float4(0.f, 0.f, 0.f, 0.f);

    #pragma unroll 4
    for (int k4 = 0; k4 < 32; k4++) {
        float4 a[4], w[4];
        #pragma unroll
        for (int r = 0; r < 4; r++) a[r] = *(float4*)&xs[r0 + r][k4 * 4];
        #pragma unroll
        for (int kk = 0; kk < 4; kk++) w[kk] = *(float4*)&ws[k4 * 4 + kk][j0];
        #pragma unroll
        for (int r = 0; r < 4; r++) {
            acc[r].x = fmaf(a[r].x, w[0].x, fmaf(a[r].y, w[1].x, fmaf(a[r].z, w[2].x, fmaf(a[r].w, w[3].x, acc[r].x))));
            acc[r].y = fmaf(a[r].x, w[0].y, fmaf(a[r].y, w[1].y, fmaf(a[r].z, w[2].y, fmaf(a[r].w, w[3].y, acc[r].y))));
            acc[r].z = fmaf(a[r].x, w[0].z, fmaf(a[r].y, w[1].z, fmaf(a[r].z, w[2].z, fmaf(a[r].w, w[3].z, acc[r].z))));
            acc[r].w = fmaf(a[r].x, w[0].w, fmaf(a[r].y, w[1].w, fmaf(a[r].z, w[2].w, fmaf(a[r].w, w[3].w, acc[r].w))));
        }
    }
    #pragma unroll
    for (int r = 0; r < 4; r++) {
        int row = rowbase + r0 + r;
        if (row < NN) {
            __half2 p0 = __floats2half2_rn(acc[r].x, acc[r].y);
            __half2 p1 = __floats2half2_rn(acc[r].z, acc[r].w);
            uint2 st;
            st.x = *(unsigned*)&p0;
            st.y = *(unsigned*)&p1;
            *(uint2*)&T[row * FH + colbase + j0] = st;
        }
    }
}

// ---------------- GEMM2: T2 = fp16( (rdo[n]*H[n,:128]) @ W2[:128,:64] ) -------
__global__ void k_gemm2(const float* __restrict__ X, const float* __restrict__ W,
                        __half* __restrict__ T) {
    __shared__ float xs[32][128];
    __shared__ float ws[128][64];
    const int t = threadIdx.x;
    const int rowbase = blockIdx.x * 32;

    for (int i = t; i < 128 * 16; i += 128) {
        int k = i >> 4, c4 = i & 15;
        *(float4*)&ws[k][c4 * 4] = *(const float4*)&W[k * FO + c4 * 4];
    }
    for (int i = t; i < 32 * 32; i += 128) {
        int r = i >> 5, c4 = i & 31;
        int row = rowbase + r;
        float4 v = make_float4(0.f, 0.f, 0.f, 0.f);
        if (row < NN) {
            v = *(const float4*)&X[row * 128 + c4 * 4];
            float sc = rsqrtf(fmaxf((float)g_cnt[NN + row], 1.0f));
            v.x *= sc; v.y *= sc; v.z *= sc; v.w *= sc;
        }
        *(float4*)&xs[r][c4 * 4] = v;
    }
    __syncthreads();

    const int tx = t & 15, ty = t >> 4;
    const int j0 = tx * 4, r0 = ty * 4;
    float4 acc[4];
    #pragma unroll
    for (int r = 0; r < 4; r++) acc[r] = make_float4(0.f, 0.f, 0.f, 0.f);

    #pragma unroll 4
    for (int k4 = 0; k4 < 32; k4++) {
        float4 a[4], w[4];
        #pragma unroll
        for (int r = 0; r < 4; r++) a[r] = *(float4*)&xs[r0 + r][k4 * 4];
        #pragma unroll
        for (int kk = 0; kk < 4; kk++) w[kk] = *(float4*)&ws[k4 * 4 + kk][j0];
        #pragma unroll
        for (int r = 0; r < 4; r++) {
            acc[r].x = fmaf(a[r].x, w[0].x, fmaf(a[r].y, w[1].x, fmaf(a[r].z, w[2].x, fmaf(a[r].w, w[3].x, acc[r].x))));
            acc[r].y = fmaf(a[r].x, w[0].y, fmaf(a[r].y, w[1].y, fmaf(a[r].z, w[2].y, fmaf(a[r].w, w[3].y, acc[r].y))));
            acc[r].z = fmaf(a[r].x, w[0].z, fmaf(a[r].y, w[1].z, fmaf(a[r].z, w[2].z, fmaf(a[r].w, w[3].z, acc[r].z))));
            acc[r].w = fmaf(a[r].x, w[0].w, fmaf(a[r].y, w[1].w, fmaf(a[r].z, w[2].w, fmaf(a[r].w, w[3].w, acc[r].w))));
        }
    }
    #pragma unroll
    for (int r = 0; r < 4; r++) {
        int row = rowbase + r0 + r;
        if (row < NN) {
            __half2 p0 = __floats2half2_rn(acc[r].x, acc[r].y);
            __half2 p1 = __floats2half2_rn(acc[r].z, acc[r].w);
            uint2 st;
            st.x = *(unsigned*)&p0;
            st.y = *(unsigned*)&p1;
            *(uint2*)&T[row * FO + j0] = st;
        }
    }
}

// ---------------- SpMM layer 1: warp-per-node over pre-scaled fp16 t1 --------
__device__ __forceinline__ void acc_half4(float4& a, uint2 v) {
    float2 f0 = __half22float2(*reinterpret_cast<__half2*>(&v.x));
    float2 f1 = __half22float2(*reinterpret_cast<__half2*>(&v.y));
    a.x += f0.x; a.y += f0.y; a.z += f1.x; a.w += f1.y;
}

__global__ void k_spmm128(const __half* __restrict__ T, const float* __restrict__ bias,
                          float* __restrict__ out) {
    int gw = (blockIdx.x * blockDim.x + threadIdx.x) >> 5;
    if (gw >= NN) return;
    int lane = threadIdx.x & 31;
    int c = lane * 4;
    const __half* Tc = T + c;
    int n = g_cnt[gw];
    if (n > STRIDE) n = STRIDE;
    const int* row = g_csr_pad + gw * STRIDE;
    float4 a0 = make_float4(0.f,0.f,0.f,0.f), a1 = a0, a2 = a0, a3 = a0;
    int i = 0;
    for (; i + 8 <= n; i += 8) {
        int s0 = row[i],   s1 = row[i+1], s2 = row[i+2], s3 = row[i+3];
        int s4 = row[i+4], s5 = row[i+5], s6 = row[i+6], s7 = row[i+7];
        uint2 v0 = *(const uint2*)(Tc + s0 * 128);
        uint2 v1 = *(const uint2*)(Tc + s1 * 128);
        uint2 v2 = *(const uint2*)(Tc + s2 * 128);
        uint2 v3 = *(const uint2*)(Tc + s3 * 128);
        uint2 v4 = *(const uint2*)(Tc + s4 * 128);
        uint2 v5 = *(const uint2*)(Tc + s5 * 128);
        uint2 v6 = *(const uint2*)(Tc + s6 * 128);
        uint2 v7 = *(const uint2*)(Tc + s7 * 128);
        acc_half4(a0, v0); acc_half4(a1, v1); acc_half4(a2, v2); acc_half4(a3, v3);
        acc_half4(a0, v4); acc_half4(a1, v5); acc_half4(a2, v6); acc_half4(a3, v7);
    }
    for (; i < n; i++) {
        uint2 v = *(const uint2*)(Tc + row[i] * 128);
        acc_half4(a0, v);
    }
    float rd = rsqrtf(fmaxf((float)n, 1.0f));
    float4 b = *(const float4*)(bias + c);
    float4 o;
    o.x = fmaxf(fmaf((a0.x + a1.x) + (a2.x + a3.x), rd, b.x), 0.f);
    o.y = fmaxf(fmaf((a0.y + a1.y) + (a2.y + a3.y), rd, b.y), 0.f);
    o.z = fmaxf(fmaf((a0.z + a1.z) + (a2.z + a3.z), rd, b.z), 0.f);
    o.w = fmaxf(fmaf((a0.w + a1.w) + (a2.w + a3.w), rd, b.w), 0.f);
    *(float4*)(out + gw * 128 + c) = o;
}

// ---------------- final SpMM: F=64 over fp16 t2 ----------------
__global__ void k_spmm64(const __half* __restrict__ T, const float* __restrict__ bias,
                         float* __restrict__ out) {
    int gw = (blockIdx.x * blockDim.x + threadIdx.x) >> 5;
    if (gw >= NN) return;
    int lane = threadIdx.x & 31;
    int c = lane * 2;
    const __half* Tc = T + c;
    int n = g_cnt[gw];
    if (n > STRIDE) n = STRIDE;
    const int* row = g_csr_pad + gw * STRIDE;
    float2 a0 = make_float2(0.f,0.f), a1 = a0, a2 = a0, a3 = a0;
    int i = 0;
    for (; i + 8 <= n; i += 8) {
        int s0 = row[i],   s1 = row[i+1], s2 = row[i+2], s3 = row[i+3];
        int s4 = row[i+4], s5 = row[i+5], s6 = row[i+6], s7 = row[i+7];
        unsigned v0 = *(const unsigned*)(Tc + s0 * 64);
        unsigned v1 = *(const unsigned*)(Tc + s1 * 64);
        unsigned v2 = *(const unsigned*)(Tc + s2 * 64);
        unsigned v3 = *(const unsigned*)(Tc + s3 * 64);
        unsigned v4 = *(const unsigned*)(Tc + s4 * 64);
        unsigned v5 = *(const unsigned*)(Tc + s5 * 64);
        unsigned v6 = *(const unsigned*)(Tc + s6 * 64);
        unsigned v7 = *(const unsigned*)(Tc + s7 * 64);
        float2 f0 = __half22float2(*reinterpret_cast<__half2*>(&v0));
        float2 f1 = __half22float2(*reinterpret_cast<__half2*>(&v1));
        float2 f2 = __half22float2(*reinterpret_cast<__half2*>(&v2));
        float2 f3 = __half22float2(*reinterpret_cast<__half2*>(&v3));
        float2 f4 = __half22float2(*reinterpret_cast<__half2*>(&v4));
        float2 f5 = __half22float2(*reinterpret_cast<__half2*>(&v5));
        float2 f6 = __half22float2(*reinterpret_cast<__half2*>(&v6));
        float2 f7 = __half22float2(*reinterpret_cast<__half2*>(&v7));
        a0.x += f0.x + f4.x; a0.y += f0.y + f4.y;
        a1.x += f1.x + f5.x; a1.y += f1.y + f5.y;
        a2.x += f2.x + f6.x; a2.y += f2.y + f6.y;
        a3.x += f3.x + f7.x; a3.y += f3.y + f7.y;
    }
    for (; i < n; i++) {
        unsigned v = *(const unsigned*)(Tc + row[i] * 64);
        float2 f = __half22float2(*reinterpret_cast<__half2*>(&v));
        a0.x += f.x; a0.y += f.y;
    }
    float rd = rsqrtf(fmaxf((float)n, 1.0f));
    float2 b = *(const float2*)(bias + c);
    float2 o;
    o.x = fmaf((a0.x + a1.x) + (a2.x + a3.x), rd, b.x);
    o.y = fmaf((a0.y + a1.y) + (a2.y + a3.y), rd, b.y);
    *(float2*)(out + gw * 64 + c) = o;
}

// ---------------- launch ----------------
extern "C" void kernel_launch(void* const* d_in, const int* in_sizes, int n_in,
                              void* d_out, int out_size) {
    const float* x   = (const float*)d_in[0];
    const int4*  src = (const int4*)d_in[1];
    const int4*  dst = (const int4*)d_in[2];
    const float* W1  = (const float*)d_in[3];
    const float* b1  = (const float*)d_in[4];
    const float* W2  = (const float*)d_in[5];
    const float* b2  = (const float*)d_in[6];
    float* out = (float*)d_out;

    __half *t1, *t2;
    float *h1;
    int* cnt;
    cudaGetSymbolAddress((void**)&t1, g_t1h);
    cudaGetSymbolAddress((void**)&h1, g_h1);
    cudaGetSymbolAddress((void**)&t2, g_t2h);
    cudaGetSymbolAddress((void**)&cnt, g_cnt);

    const int N4 = NE / 4;

    // fork
    cudaEventRecord(g_e1, 0);
    cudaStreamWaitEvent(g_s2, g_e1, 0);

    // main: memset both counter regions, then the full fill
    cudaMemsetAsync(cnt, 0, 2 * NN * sizeof(int), 0);
    cudaEventRecord(g_eM, 0);
    k_fill<<<(N4 + 255) / 256, 256>>>(src, dst);

    // s2: gemm1 (graph-independent) -> hist (after memset) -> scale t1
    k_gemm1<<<dim3((NN + 31) / 32, FH / 64), 128, 0, g_s2>>>(x, W1, t1);
    cudaStreamWaitEvent(g_s2, g_eM, 0);
    k_hist<<<(N4 + 255) / 256, 256, 0, g_s2>>>(src);
    k_scale_t1<<<(NN * FH / 4 + 255) / 256, 256, 0, g_s2>>>();
    cudaEventRecord(g_eS, g_s2);

    // main: join, then the 3-kernel dense tail
    cudaStreamWaitEvent(0, g_eS, 0);
    k_spmm128<<<(NN * 32 + 255) / 256, 256>>>(t1, b1, h1);
    k_gemm2<<<(NN + 31) / 32, 128>>>(h1, W2, t2);
    k_spmm64<<<(NN * 32 + 255) / 256, 256>>>(t2, b2, out);
}

// round 15
// speedup vs baseline: 1.2145x; 1.1716x over previous
#include <cuda_runtime.h>
#include <cuda_fp16.h>

#define NN 10000
#define NE 640000
#define FH 128
#define FO 64
#define STRIDE 192
#define N4 (NE / 4)          // 160000 int4 edges
#define NCHUNK 625           // N4 / 256 per list
#define GEMM1_TILES 626      // 313 row-blocks x 2 col-blocks

// ---------------- scratch (static __device__, no allocation) ----------------
// g_cnt = [cursor/deg_in (NN) | deg_out (NN) | wq | bar | pad...]; one memset.
#define WQ_IDX  (2 * NN)
#define BAR_IDX (2 * NN + 1)
__device__ __align__(16) int g_cnt[2 * NN + 8];
__device__ int g_csr_pad[NN * STRIDE];
__device__ float g_rdo[NN];
__device__ __align__(16) __half g_t1h[NN * FH];   // fp16 x@W1 (unscaled)
__device__ __align__(16) __half g_t2h[NN * FO];   // fp16 (rdo*h1)@W2

// ---------------- grid barrier (counter zeroed by host memset per launch) ---
__device__ __forceinline__ void grid_bar(unsigned phase, unsigned G) {
    __syncthreads();
    if (threadIdx.x == 0) {
        __threadfence();
        atomicAdd((unsigned*)&g_cnt[BAR_IDX], 1u);
        unsigned tgt = phase * G;
        while (*((volatile unsigned*)&g_cnt[BAR_IDX]) < tgt) { }
    }
    __syncthreads();
}

// ---------------- edge accumulate helpers ----------------
__device__ __forceinline__ void acc_edge(float4& a, uint2 v, float sc) {
    float2 f0 = __half22float2(*reinterpret_cast<__half2*>(&v.x));
    float2 f1 = __half22float2(*reinterpret_cast<__half2*>(&v.y));
    a.x = fmaf(sc, f0.x, a.x); a.y = fmaf(sc, f0.y, a.y);
    a.z = fmaf(sc, f1.x, a.z); a.w = fmaf(sc, f1.y, a.w);
}

__global__ __launch_bounds__(256)
void k_mega(const float* __restrict__ x, const int4* __restrict__ src4,
            const int4* __restrict__ dst4, const float* __restrict__ W1,
            const float* __restrict__ b1, const float* __restrict__ W2,
            const float* __restrict__ b2, float* __restrict__ out) {
    __shared__ float s_xs[32 * 128];   // 16 KB
    __shared__ float s_ws[128 * 64];   // 32 KB
    __shared__ int s_chunk;
    const int tid = threadIdx.x, b = blockIdx.x;
    const unsigned G = gridDim.x;

    // ================= P1: gemm1 (half the blocks) + fill/hist work pool =====
    const int nG = G / 2;
    if (b < nG) {
        for (int t = b; t < GEMM1_TILES; t += nG) {
            const int rowbase = (t >> 1) * 32, colbase = (t & 1) * 64;
            for (int i = tid; i < 2048; i += 256) {            // W1 tile 128x64
                int k = i >> 4, c4 = i & 15;
                *(float4*)&s_ws[k * 64 + c4 * 4] =
                    *(const float4*)&W1[k * FH + colbase + c4 * 4];
            }
            for (int i = tid; i < 1024; i += 256) {            // X tile 32x128
                int r = i >> 5, c4 = i & 31;
                int row = rowbase + r;
                float4 v = make_float4(0.f, 0.f, 0.f, 0.f);
                if (row < NN) v = *(const float4*)&x[row * 128 + c4 * 4];
                *(float4*)&s_xs[r * 128 + c4 * 4] = v;
            }
            __syncthreads();
            const int tx = tid & 15, ty = tid >> 4;
            const int j0 = tx * 4, r0 = ty * 2;
            float4 acc0 = make_float4(0.f,0.f,0.f,0.f), acc1 = acc0;
            #pragma unroll 4
            for (int k4 = 0; k4 < 32; k4++) {
                float4 a0 = *(float4*)&s_xs[(r0 + 0) * 128 + k4 * 4];
                float4 a1 = *(float4*)&s_xs[(r0 + 1) * 128 + k4 * 4];
                float4 w0 = *(float4*)&s_ws[(k4 * 4 + 0) * 64 + j0];
                float4 w1 = *(float4*)&s_ws[(k4 * 4 + 1) * 64 + j0];
                float4 w2 = *(float4*)&s_ws[(k4 * 4 + 2) * 64 + j0];
                float4 w3 = *(float4*)&s_ws[(k4 * 4 + 3) * 64 + j0];
                acc0.x = fmaf(a0.x,w0.x, fmaf(a0.y,w1.x, fmaf(a0.z,w2.x, fmaf(a0.w,w3.x, acc0.x))));
                acc0.y = fmaf(a0.x,w0.y, fmaf(a0.y,w1.y, fmaf(a0.z,w2.y, fmaf(a0.w,w3.y, acc0.y))));
                acc0.z = fmaf(a0.x,w0.z, fmaf(a0.y,w1.z, fmaf(a0.z,w2.z, fmaf(a0.w,w3.z, acc0.z))));
                acc0.w = fmaf(a0.x,w0.w, fmaf(a0.y,w1.w, fmaf(a0.z,w2.w, fmaf(a0.w,w3.w, acc0.w))));
                acc1.x = fmaf(a1.x,w0.x, fmaf(a1.y,w1.x, fmaf(a1.z,w2.x, fmaf(a1.w,w3.x, acc1.x))));
                acc1.y = fmaf(a1.x,w0.y, fmaf(a1.y,w1.y, fmaf(a1.z,w2.y, fmaf(a1.w,w3.y, acc1.y))));
                acc1.z = fmaf(a1.x,w0.z, fmaf(a1.y,w1.z, fmaf(a1.z,w2.z, fmaf(a1.w,w3.z, acc1.z))));
                acc1.w = fmaf(a1.x,w0.w, fmaf(a1.y,w1.w, fmaf(a1.z,w2.w, fmaf(a1.w,w3.w, acc1.w))));
            }
            int row0 = rowbase + r0;
            if (row0 < NN) {
                __half2 p0 = __floats2half2_rn(acc0.x, acc0.y);
                __half2 p1 = __floats2half2_rn(acc0.z, acc0.w);
                uint2 st; st.x = *(unsigned*)&p0; st.y = *(unsigned*)&p1;
                *(uint2*)&g_t1h[row0 * FH + colbase + j0] = st;
            }
            if (row0 + 1 < NN) {
                __half2 p0 = __floats2half2_rn(acc1.x, acc1.y);
                __half2 p1 = __floats2half2_rn(acc1.z, acc1.w);
                uint2 st; st.x = *(unsigned*)&p0; st.y = *(unsigned*)&p1;
                *(uint2*)&g_t1h[(row0 + 1) * FH + colbase + j0] = st;
            }
            __syncthreads();
        }
    }
    // work pool: chunks [0,625) = fill, [625,1250) = hist; all blocks drain it
    for (;;) {
        if (tid == 0) s_chunk = atomicAdd(&g_cnt[WQ_IDX], 1);
        __syncthreads();
        int c = s_chunk;
        __syncthreads();
        if (c >= 2 * NCHUNK) break;
        if (c < NCHUNK) {
            int e = c * 256 + tid;
            int4 s = src4[e], d = dst4[e];
            int p0 = atomicAdd(&g_cnt[d.x], 1);
            int p1 = atomicAdd(&g_cnt[d.y], 1);
            int p2 = atomicAdd(&g_cnt[d.z], 1);
            int p3 = atomicAdd(&g_cnt[d.w], 1);
            if (p0 < STRIDE) g_csr_pad[d.x * STRIDE + p0] = s.x;
            if (p1 < STRIDE) g_csr_pad[d.y * STRIDE + p1] = s.y;
            if (p2 < STRIDE) g_csr_pad[d.z * STRIDE + p2] = s.z;
            if (p3 < STRIDE) g_csr_pad[d.w * STRIDE + p3] = s.w;
        } else {
            int e = (c - NCHUNK) * 256 + tid;
            int4 s = src4[e];
            atomicAdd(&g_cnt[NN + s.x], 1);
            atomicAdd(&g_cnt[NN + s.y], 1);
            atomicAdd(&g_cnt[NN + s.z], 1);
            atomicAdd(&g_cnt[NN + s.w], 1);
        }
    }
    grid_bar(1, G);

    // ================= P2a: rdo table ========================================
    for (int i = b * 256 + tid; i < NN; i += G * 256)
        g_rdo[i] = rsqrtf(fmaxf((float)__ldcg(&g_cnt[NN + i]), 1.0f));
    grid_bar(2, G);

    // ================= P2: fused spmm128 + layer-2 GEMV ======================
    for (int i = tid; i < 2048; i += 256)                      // W2 -> smem
        *(float4*)&s_ws[i * 4] = ((const float4*)W2)[i];
    __syncthreads();

    const int w = tid >> 5, lane = tid & 31;
    const int c4o = lane * 4;
    const __half* Tc = g_t1h + c4o;
    float* stage = &s_xs[w * 128];
    const int totalWarps = G * 8;

    for (int node = b * 8 + w; node < NN; node += totalWarps) {
        int n = __ldcg(&g_cnt[node]); if (n > STRIDE) n = STRIDE;
        const int* row = g_csr_pad + node * STRIDE;
        float4 a0 = make_float4(0.f,0.f,0.f,0.f), a1 = a0, a2 = a0, a3 = a0;
        int i = 0;
        for (; i + 8 <= n; i += 8) {
            int s0 = row[i],   s1 = row[i+1], s2 = row[i+2], s3 = row[i+3];
            int s4 = row[i+4], s5 = row[i+5], s6 = row[i+6], s7 = row[i+7];
            uint2 v0 = *(const uint2*)(Tc + s0 * 128);
            uint2 v1 = *(const uint2*)(Tc + s1 * 128);
            uint2 v2 = *(const uint2*)(Tc + s2 * 128);
            uint2 v3 = *(const uint2*)(Tc + s3 * 128);
            uint2 v4 = *(const uint2*)(Tc + s4 * 128);
            uint2 v5 = *(const uint2*)(Tc + s5 * 128);
            uint2 v6 = *(const uint2*)(Tc + s6 * 128);
            uint2 v7 = *(const uint2*)(Tc + s7 * 128);
            float r0 = g_rdo[s0], r1 = g_rdo[s1], r2 = g_rdo[s2], r3 = g_rdo[s3];
            float r4 = g_rdo[s4], r5 = g_rdo[s5], r6 = g_rdo[s6], r7 = g_rdo[s7];
            acc_edge(a0, v0, r0); acc_edge(a1, v1, r1);
            acc_edge(a2, v2, r2); acc_edge(a3, v3, r3);
            acc_edge(a0, v4, r4); acc_edge(a1, v5, r5);
            acc_edge(a2, v6, r6); acc_edge(a3, v7, r7);
        }
        for (; i < n; i++) {
            int s0 = row[i];
            uint2 v = *(const uint2*)(Tc + s0 * 128);
            acc_edge(a0, v, g_rdo[s0]);
        }
        float rd = rsqrtf(fmaxf((float)n, 1.0f));
        float ro = g_rdo[node];
        float4 bb = *(const float4*)&b1[c4o];
        float4 h;
        h.x = ro * fmaxf(fmaf((a0.x + a1.x) + (a2.x + a3.x), rd, bb.x), 0.f);
        h.y = ro * fmaxf(fmaf((a0.y + a1.y) + (a2.y + a3.y), rd, bb.y), 0.f);
        h.z = ro * fmaxf(fmaf((a0.z + a1.z) + (a2.z + a3.z), rd, bb.z), 0.f);
        h.w = ro * fmaxf(fmaf((a0.w + a1.w) + (a2.w + a3.w), rd, bb.w), 0.f);
        *(float4*)&stage[c4o] = h;
        __syncwarp();
        // GEMV: t2[node][j] = sum_k h[k] * W2[k][j], 2 cols per lane
        int j0 = lane * 2;
        float2 acc = make_float2(0.f, 0.f);
        #pragma unroll 8
        for (int k = 0; k < 128; k++) {
            float a = stage[k];
            float2 wv = *(float2*)&s_ws[k * 64 + j0];
            acc.x = fmaf(a, wv.x, acc.x);
            acc.y = fmaf(a, wv.y, acc.y);
        }
        __half2 p = __floats2half2_rn(acc.x, acc.y);
        *(unsigned*)&g_t2h[node * FO + j0] = *(unsigned*)&p;
        __syncwarp();
    }
    grid_bar(3, G);

    // ================= P3: spmm64 -> out =====================================
    const __half* T2c = g_t2h + lane * 2;
    for (int node = b * 8 + w; node < NN; node += totalWarps) {
        int n = __ldcg(&g_cnt[node]); if (n > STRIDE) n = STRIDE;
        const int* row = g_csr_pad + node * STRIDE;
        float2 a0 = make_float2(0.f,0.f), a1 = a0, a2 = a0, a3 = a0;
        int i = 0;
        for (; i + 8 <= n; i += 8) {
            int s0 = row[i],   s1 = row[i+1], s2 = row[i+2], s3 = row[i+3];
            int s4 = row[i+4], s5 = row[i+5], s6 = row[i+6], s7 = row[i+7];
            unsigned v0 = *(const unsigned*)(T2c + s0 * 64);
            unsigned v1 = *(const unsigned*)(T2c + s1 * 64);
            unsigned v2 = *(const unsigned*)(T2c + s2 * 64);
            unsigned v3 = *(const unsigned*)(T2c + s3 * 64);
            unsigned v4 = *(const unsigned*)(T2c + s4 * 64);
            unsigned v5 = *(const unsigned*)(T2c + s5 * 64);
            unsigned v6 = *(const unsigned*)(T2c + s6 * 64);
            unsigned v7 = *(const unsigned*)(T2c + s7 * 64);
            float2 f0 = __half22float2(*reinterpret_cast<__half2*>(&v0));
            float2 f1 = __half22float2(*reinterpret_cast<__half2*>(&v1));
            float2 f2 = __half22float2(*reinterpret_cast<__half2*>(&v2));
            float2 f3 = __half22float2(*reinterpret_cast<__half2*>(&v3));
            float2 f4 = __half22float2(*reinterpret_cast<__half2*>(&v4));
            float2 f5 = __half22float2(*reinterpret_cast<__half2*>(&v5));
            float2 f6 = __half22float2(*reinterpret_cast<__half2*>(&v6));
            float2 f7 = __half22float2(*reinterpret_cast<__half2*>(&v7));
            a0.x += f0.x + f4.x; a0.y += f0.y + f4.y;
            a1.x += f1.x + f5.x; a1.y += f1.y + f5.y;
            a2.x += f2.x + f6.x; a2.y += f2.y + f6.y;
            a3.x += f3.x + f7.x; a3.y += f3.y + f7.y;
        }
        for (; i < n; i++) {
            unsigned v = *(const unsigned*)(T2c + row[i] * 64);
            float2 f = __half22float2(*reinterpret_cast<__half2*>(&v));
            a0.x += f.x; a0.y += f.y;
        }
        float rd = rsqrtf(fmaxf((float)n, 1.0f));
        float2 bb = *(const float2*)&b2[lane * 2];
        float2 o;
        o.x = fmaf((a0.x + a1.x) + (a2.x + a3.x), rd, bb.x);
        o.y = fmaf((a0.y + a1.y) + (a2.y + a3.y), rd, bb.y);
        *(float2*)&out[node * FO + lane * 2] = o;
    }
}

// ---------------- launch ----------------
extern "C" void kernel_launch(void* const* d_in, const int* in_sizes, int n_in,
                              void* d_out, int out_size) {
    const float* x   = (const float*)d_in[0];
    const int4*  src = (const int4*)d_in[1];
    const int4*  dst = (const int4*)d_in[2];
    const float* W1  = (const float*)d_in[3];
    const float* b1  = (const float*)d_in[4];
    const float* W2  = (const float*)d_in[5];
    const float* b2  = (const float*)d_in[6];
    float* out = (float*)d_out;

    int* cnt;
    cudaGetSymbolAddress((void**)&cnt, g_cnt);

    int nSM = 148, bps = 1;
    cudaDeviceGetAttribute(&nSM, cudaDevAttrMultiProcessorCount, 0);
    cudaOccupancyMaxActiveBlocksPerMultiprocessor(&bps, k_mega, 256, 0);
    if (bps < 1) bps = 1;
    int G = nSM * bps;

    // zero counters + work queue + barrier, then the single persistent kernel
    cudaMemsetAsync(cnt, 0, (2 * NN + 8) * sizeof(int), 0);
    k_mega<<<G, 256>>>(x, src, dst, W1, b1, W2, b2, out);
}